// round 15
// baseline (speedup 1.0000x reference)
#include <cuda_runtime.h>
#include <cuda_bf16.h>
#include <cstdint>

#define VOCAB 256
#define CHARS 20
#define ROWS_PER_TILE 32
#define THREADS 256
#define HIST_FLOATS (ROWS_PER_TILE * VOCAB)          // 8192
#define HIST_BYTES  (HIST_FLOATS * 4)                // 32768
#define TASKS       (ROWS_PER_TILE * CHARS)          // 640
#define GRID_BLOCKS 444                              // 3 resident * 148 SMs

__device__ __forceinline__ uint32_t smem_u32(const void* p) {
    uint32_t a;
    asm("{ .reg .u64 t; cvta.to.shared.u64 t, %1; cvt.u32.u64 %0, t; }"
        : "=r"(a) : "l"(p));
    return a;
}

__device__ __forceinline__ int ldg_pol(const int* p, uint64_t pol) {
    int v;
    asm("ld.global.nc.L2::cache_hint.b32 %0, [%1], %2;"
        : "=r"(v) : "l"(p), "l"(pol));
    return v;
}

__global__ void __launch_bounds__(THREADS) fofe_rezero_kernel(
    const int* __restrict__ char_ids,
    const float* __restrict__ forgetting_factor,
    float* __restrict__ out,
    int n_tiles)
{
    __shared__ __align__(128) float hist[2][HIST_FLOATS];
    __shared__ float pw_s[CHARS];

    const int t = threadIdx.x;

    // R7-best residency policy: 9/16 of output protected (evict_last),
    // 7/16 sacrificial stream (evict_first), ids pinned.
    uint64_t pol_last, pol_first;
    asm("createpolicy.fractional.L2::evict_last.b64 %0, 1.0;"  : "=l"(pol_last));
    asm("createpolicy.fractional.L2::evict_first.b64 %0, 1.0;" : "=l"(pol_first));

    if (t < CHARS) {
        const float alpha = __ldg(forgetting_factor);
        float p = 1.f;
        const int e = (CHARS - 1) - t;
        for (int i = 0; i < e; ++i) p *= alpha;
        pw_s[t] = p;
    }

    // Loop-invariant task mapping: tasks t, t+256, t+512 (<640).
    const int  rA = t / CHARS,  kA = t - (t / CHARS) * CHARS;
    const int  slotA = rA * VOCAB;
    const int  tB = t + THREADS;
    const int  rB = tB / CHARS, kB = tB - (tB / CHARS) * CHARS;
    const int  slotB = rB * VOCAB;
    const int  tC = t + 2 * THREADS;
    const bool hasC = tC < TASKS;
    const int  rC = tC / CHARS, kC = tC - (tC / CHARS) * CHARS;
    const int  slotC = rC * VOCAB;

    // One-time full zero of BOTH buffers; afterwards only touched slots are
    // ever nonzero, and each buffer reuse re-zeros exactly those (induction).
    {
        float4* hz = reinterpret_cast<float4*>(hist);
        const float4 z = make_float4(0.f, 0.f, 0.f, 0.f);
#pragma unroll
        for (int i = 0; i < (2 * HIST_FLOATS / 4) / THREADS; ++i)
            hz[t + i * THREADS] = z;
    }

    int tile = blockIdx.x;

    // Per-buffer id registers (current) and touched-slot history (previous
    // use of that buffer).  History starts at 0: re-zeroing slot 0 of an
    // all-zero buffer is harmless.
    int idA0 = 0, idB0 = 0, idC0 = 0, idA1 = 0, idB1 = 0, idC1 = 0;
    int zA0 = 0,  zB0 = 0,  zC0 = 0,  zA1 = 0,  zB1 = 0,  zC1 = 0;

    if (tile < n_tiles) {
        const int* base = char_ids + (size_t)tile * TASKS;
        idA0 = ldg_pol(base + t, pol_last);
        idB0 = ldg_pol(base + tB, pol_last);
        if (hasC) idC0 = ldg_pol(base + tC, pol_last);
    }

    __syncthreads();   // pw_s + zeroed buffers ready
    const float pwA = pw_s[kA];
    const float pwB = pw_s[kB];
    const float pwC = hasC ? pw_s[kC] : 0.f;

    for (;;) {
        // ---------------- buffer 0 ----------------
        if (tile >= n_tiles) break;
        {
            float* h = hist[0];
            if (t == 0)
                asm volatile("cp.async.bulk.wait_group.read 1;" ::: "memory");
            __syncthreads();

            // Re-zero only the slots this thread touched last time buf0 was
            // used (idempotent across threads; union covers all touched).
            h[slotA + zA0] = 0.f;
            h[slotB + zB0] = 0.f;
            if (hasC) h[slotC + zC0] = 0.f;
            __syncthreads();

            atomicAdd(&h[slotA + idA0], pwA);
            atomicAdd(&h[slotB + idB0], pwB);
            if (hasC) atomicAdd(&h[slotC + idC0], pwC);
            zA0 = idA0; zB0 = idB0; zC0 = idC0;

            const int nt = tile + GRID_BLOCKS;
            if (nt < n_tiles) {   // prefetch ids for buffer 1's tile
                const int* base = char_ids + (size_t)nt * TASKS;
                idA1 = ldg_pol(base + t, pol_last);
                idB1 = ldg_pol(base + tB, pol_last);
                if (hasC) idC1 = ldg_pol(base + tC, pol_last);
            }
            __syncthreads();

            if (t == 0) {
                asm volatile("fence.proxy.async.shared::cta;" ::: "memory");
                const uint32_t src = smem_u32(h);
                float* dst = out + (size_t)tile * HIST_FLOATS;
                const uint64_t pol = ((tile & 15) < 9) ? pol_last : pol_first;
                asm volatile(
                    "cp.async.bulk.global.shared::cta.bulk_group.L2::cache_hint"
                    " [%0], [%1], %2, %3;"
                    :: "l"(dst), "r"(src), "n"(HIST_BYTES), "l"(pol) : "memory");
                asm volatile("cp.async.bulk.commit_group;" ::: "memory");
            }
            tile = nt;
        }

        // ---------------- buffer 1 ----------------
        if (tile >= n_tiles) break;
        {
            float* h = hist[1];
            if (t == 0)
                asm volatile("cp.async.bulk.wait_group.read 1;" ::: "memory");
            __syncthreads();

            h[slotA + zA1] = 0.f;
            h[slotB + zB1] = 0.f;
            if (hasC) h[slotC + zC1] = 0.f;
            __syncthreads();

            atomicAdd(&h[slotA + idA1], pwA);
            atomicAdd(&h[slotB + idB1], pwB);
            if (hasC) atomicAdd(&h[slotC + idC1], pwC);
            zA1 = idA1; zB1 = idB1; zC1 = idC1;

            const int nt = tile + GRID_BLOCKS;
            if (nt < n_tiles) {   // prefetch ids for buffer 0's tile
                const int* base = char_ids + (size_t)nt * TASKS;
                idA0 = ldg_pol(base + t, pol_last);
                idB0 = ldg_pol(base + tB, pol_last);
                if (hasC) idC0 = ldg_pol(base + tC, pol_last);
            }
            __syncthreads();

            if (t == 0) {
                asm volatile("fence.proxy.async.shared::cta;" ::: "memory");
                const uint32_t src = smem_u32(h);
                float* dst = out + (size_t)tile * HIST_FLOATS;
                const uint64_t pol = ((tile & 15) < 9) ? pol_last : pol_first;
                asm volatile(
                    "cp.async.bulk.global.shared::cta.bulk_group.L2::cache_hint"
                    " [%0], [%1], %2, %3;"
                    :: "l"(dst), "r"(src), "n"(HIST_BYTES), "l"(pol) : "memory");
                asm volatile("cp.async.bulk.commit_group;" ::: "memory");
            }
            tile = nt;
        }
    }

    // Drain all outstanding bulk stores before exit
    if (t == 0)
        asm volatile("cp.async.bulk.wait_group 0;" ::: "memory");
}

extern "C" void kernel_launch(void* const* d_in, const int* in_sizes, int n_in,
                              void* d_out, int out_size) {
    const int* char_ids;
    const float* ff;
    if (in_sizes[0] > in_sizes[1]) {
        char_ids = (const int*)d_in[0];
        ff = (const float*)d_in[1];
    } else {
        char_ids = (const int*)d_in[1];
        ff = (const float*)d_in[0];
    }
    float* out = (float*)d_out;

    const int n_rows  = out_size / VOCAB;              // 131072
    const int n_tiles = n_rows / ROWS_PER_TILE;        // 4096

    fofe_rezero_kernel<<<GRID_BLOCKS, THREADS>>>(char_ids, ff, out, n_tiles);
}

// round 16
// speedup vs baseline: 1.0094x; 1.0094x over previous
#include <cuda_runtime.h>
#include <cuda_bf16.h>
#include <cstdint>

#define VOCAB 256
#define CHARS 20
#define ROWS_PER_TILE 32
#define THREADS 256
#define HIST_FLOATS (ROWS_PER_TILE * VOCAB)          // 8192
#define HIST_BYTES  (HIST_FLOATS * 4)                // 32768
#define TASKS       (ROWS_PER_TILE * CHARS)          // 640
#define VEC_THREADS (TASKS / 4)                      // 160 int4 loads
#define GRID_BLOCKS 444                              // 3 resident * 148 SMs

__device__ __forceinline__ uint32_t smem_u32(const void* p) {
    uint32_t a;
    asm("{ .reg .u64 t; cvta.to.shared.u64 t, %1; cvt.u32.u64 %0, t; }"
        : "=r"(a) : "l"(p));
    return a;
}

__device__ __forceinline__ int4 ldg4_pol(const int4* p, uint64_t pol) {
    int4 v;
    asm("ld.global.nc.L2::cache_hint.v4.b32 {%0,%1,%2,%3}, [%4], %5;"
        : "=r"(v.x), "=r"(v.y), "=r"(v.z), "=r"(v.w) : "l"(p), "l"(pol));
    return v;
}

__global__ void __launch_bounds__(THREADS) fofe_vec4_kernel(
    const int* __restrict__ char_ids,
    const float* __restrict__ forgetting_factor,
    float* __restrict__ out,
    int n_tiles)
{
    __shared__ __align__(128) float hist[2][HIST_FLOATS];
    __shared__ float pw_s[CHARS];

    const int t = threadIdx.x;

    // Best-measured residency policy (R7): 9/16 output protected via
    // evict_last, 7/16 sacrificial evict_first stream, ids pinned.
    uint64_t pol_last, pol_first;
    asm("createpolicy.fractional.L2::evict_last.b64 %0, 1.0;"  : "=l"(pol_last));
    asm("createpolicy.fractional.L2::evict_first.b64 %0, 1.0;" : "=l"(pol_first));

    if (t < CHARS) {
        const float alpha = __ldg(forgetting_factor);
        float p = 1.f;
        const int e = (CHARS - 1) - t;
        for (int i = 0; i < e; ++i) p *= alpha;
        pw_s[t] = p;
    }

    // Vectorized task mapping: thread t < 160 owns tasks 4t..4t+3, all in
    // the SAME row (20 % 4 == 0): row = t/5, chars k0..k0+3, k0 = (4t)%20.
    const bool active = t < VEC_THREADS;
    const int  row  = t / 5;
    const int  slot = row * VOCAB;
    const int  k0   = (4 * t) % CHARS;

    // One-time full zero of both buffers; afterwards sparse re-zero by
    // induction (only previously-touched slots are ever nonzero).
    {
        float4* hz = reinterpret_cast<float4*>(hist);
        const float4 z = make_float4(0.f, 0.f, 0.f, 0.f);
#pragma unroll
        for (int i = 0; i < (2 * HIST_FLOATS / 4) / THREADS; ++i)
            hz[t + i * THREADS] = z;
    }

    int tile = blockIdx.x;

    int4 id0 = make_int4(0, 0, 0, 0), id1 = make_int4(0, 0, 0, 0);
    int4 z0  = make_int4(0, 0, 0, 0), z1  = make_int4(0, 0, 0, 0);

    if (active && tile < n_tiles) {
        const int4* base = reinterpret_cast<const int4*>(
            char_ids + (size_t)tile * TASKS);
        id0 = ldg4_pol(base + t, pol_last);
    }

    __syncthreads();   // pw_s + zeroed buffers ready
    float pw0 = 0.f, pw1 = 0.f, pw2 = 0.f, pw3 = 0.f;
    if (active) {
        pw0 = pw_s[k0]; pw1 = pw_s[k0 + 1];
        pw2 = pw_s[k0 + 2]; pw3 = pw_s[k0 + 3];
    }

    for (;;) {
        // ---------------- buffer 0 ----------------
        if (tile >= n_tiles) break;
        {
            float* h = hist[0];
            if (t == 0)
                asm volatile("cp.async.bulk.wait_group.read 1;" ::: "memory");
            __syncthreads();

            if (active) {   // sparse re-zero of previously-touched slots
                h[slot + z0.x] = 0.f; h[slot + z0.y] = 0.f;
                h[slot + z0.z] = 0.f; h[slot + z0.w] = 0.f;
            }
            __syncthreads();

            if (active) {
                atomicAdd(&h[slot + id0.x], pw0);
                atomicAdd(&h[slot + id0.y], pw1);
                atomicAdd(&h[slot + id0.z], pw2);
                atomicAdd(&h[slot + id0.w], pw3);
                z0 = id0;
            }

            const int nt = tile + GRID_BLOCKS;
            if (active && nt < n_tiles) {   // prefetch buffer-1 tile ids
                const int4* base = reinterpret_cast<const int4*>(
                    char_ids + (size_t)nt * TASKS);
                id1 = ldg4_pol(base + t, pol_last);
            }
            __syncthreads();

            if (t == 0) {
                asm volatile("fence.proxy.async.shared::cta;" ::: "memory");
                const uint32_t src = smem_u32(h);
                float* dst = out + (size_t)tile * HIST_FLOATS;
                const uint64_t pol = ((tile & 15) < 9) ? pol_last : pol_first;
                asm volatile(
                    "cp.async.bulk.global.shared::cta.bulk_group.L2::cache_hint"
                    " [%0], [%1], %2, %3;"
                    :: "l"(dst), "r"(src), "n"(HIST_BYTES), "l"(pol) : "memory");
                asm volatile("cp.async.bulk.commit_group;" ::: "memory");
            }
            tile = nt;
        }

        // ---------------- buffer 1 ----------------
        if (tile >= n_tiles) break;
        {
            float* h = hist[1];
            if (t == 0)
                asm volatile("cp.async.bulk.wait_group.read 1;" ::: "memory");
            __syncthreads();

            if (active) {
                h[slot + z1.x] = 0.f; h[slot + z1.y] = 0.f;
                h[slot + z1.z] = 0.f; h[slot + z1.w] = 0.f;
            }
            __syncthreads();

            if (active) {
                atomicAdd(&h[slot + id1.x], pw0);
                atomicAdd(&h[slot + id1.y], pw1);
                atomicAdd(&h[slot + id1.z], pw2);
                atomicAdd(&h[slot + id1.w], pw3);
                z1 = id1;
            }

            const int nt = tile + GRID_BLOCKS;
            if (active && nt < n_tiles) {   // prefetch buffer-0 tile ids
                const int4* base = reinterpret_cast<const int4*>(
                    char_ids + (size_t)nt * TASKS);
                id0 = ldg4_pol(base + t, pol_last);
            }
            __syncthreads();

            if (t == 0) {
                asm volatile("fence.proxy.async.shared::cta;" ::: "memory");
                const uint32_t src = smem_u32(h);
                float* dst = out + (size_t)tile * HIST_FLOATS;
                const uint64_t pol = ((tile & 15) < 9) ? pol_last : pol_first;
                asm volatile(
                    "cp.async.bulk.global.shared::cta.bulk_group.L2::cache_hint"
                    " [%0], [%1], %2, %3;"
                    :: "l"(dst), "r"(src), "n"(HIST_BYTES), "l"(pol) : "memory");
                asm volatile("cp.async.bulk.commit_group;" ::: "memory");
            }
            tile = nt;
        }
    }

    // Drain all outstanding bulk stores before exit
    if (t == 0)
        asm volatile("cp.async.bulk.wait_group 0;" ::: "memory");
}

extern "C" void kernel_launch(void* const* d_in, const int* in_sizes, int n_in,
                              void* d_out, int out_size) {
    const int* char_ids;
    const float* ff;
    if (in_sizes[0] > in_sizes[1]) {
        char_ids = (const int*)d_in[0];
        ff = (const float*)d_in[1];
    } else {
        char_ids = (const int*)d_in[1];
        ff = (const float*)d_in[0];
    }
    float* out = (float*)d_out;

    const int n_rows  = out_size / VOCAB;              // 131072
    const int n_tiles = n_rows / ROWS_PER_TILE;        // 4096

    fofe_vec4_kernel<<<GRID_BLOCKS, THREADS>>>(char_ids, ff, out, n_tiles);
}